// round 15
// baseline (speedup 1.0000x reference)
#include <cuda_runtime.h>
#include <cuda_fp16.h>
#include <cstdint>

// PQLinear: out[8192,4096] = X[8192,4096] @ W^T (W gathered from PQ codebooks).
// R15: R14's cross-chunk k0 prefetch made RACE-FREE. The single per-chunk
// barrier moves mid-chunk: kg0,kg1 -> cp_wait<0> + __syncthreads -> issue
// load(i+2) -> kg2, kg3(+prefetch k0 of chunk i+1). The barrier now sits
// between everyone's wait on chunk i+1's copies and the kg=3 read of them
// (visibility), and between iter i-1's last smem reads and the overwrite
// (anti-dep). Same sync count as R14; R14's rel_err drift should revert.

#define M_TOT 8192
#define N_TOT 4096
#define K_TOT 4096
#define BM 128
#define BN 128
#define BK 64                         // halves per chunk (128 B rows)
#define STAGES 3
#define NCHUNK (K_TOT / BK)           // 64
#define A_STAGE_BYTES (BM * 128)      // 16384
#define B_STAGE_BYTES (BN * 128)      // 16384
#define SM_B_OFF (STAGES * A_STAGE_BYTES)
#define SMEM_BYTES (STAGES * (A_STAGE_BYTES + B_STAGE_BYTES))   // 98304

__device__ __half g_Xh[(size_t)M_TOT * K_TOT];   // 64 MB fp16 X
__device__ __half g_Wh[(size_t)N_TOT * K_TOT];   // 32 MB fp16 gathered W

// ---------------- helpers ----------------
__device__ __forceinline__ uint32_t smem_u32(const void* p) {
    uint32_t a;
    asm("{ .reg .u64 t; cvta.to.shared.u64 t, %1; cvt.u32.u64 %0, t; }" : "=r"(a) : "l"(p));
    return a;
}
__device__ __forceinline__ void cpa16(uint32_t saddr, const void* gaddr) {
    asm volatile("cp.async.cg.shared.global [%0], [%1], 16;" :: "r"(saddr), "l"(gaddr));
}
__device__ __forceinline__ void cp_commit() { asm volatile("cp.async.commit_group;" ::: "memory"); }
template <int N>
__device__ __forceinline__ void cp_wait() { asm volatile("cp.async.wait_group %0;" :: "n"(N) : "memory"); }

__device__ __forceinline__ void ldsm4(uint32_t* r, uint32_t addr) {
    asm volatile("ldmatrix.sync.aligned.m8n8.x4.shared.b16 {%0,%1,%2,%3}, [%4];"
                 : "=r"(r[0]), "=r"(r[1]), "=r"(r[2]), "=r"(r[3]) : "r"(addr));
}
__device__ __forceinline__ void mma_f16(float* c, const uint32_t* a, const uint32_t* b) {
    asm volatile(
        "mma.sync.aligned.m16n8k16.row.col.f32.f16.f16.f32 "
        "{%0,%1,%2,%3}, {%4,%5,%6,%7}, {%8,%9}, {%0,%1,%2,%3};"
        : "+f"(c[0]), "+f"(c[1]), "+f"(c[2]), "+f"(c[3])
        : "r"(a[0]), "r"(a[1]), "r"(a[2]), "r"(a[3]), "r"(b[0]), "r"(b[1]));
}

// ---------------- fused prep, interleaved by bid%3 ----------------
__global__ void prep_fused_kernel(const float* __restrict__ x,
                                  const float* __restrict__ cb,
                                  const int* __restrict__ assign) {
    const int bid = blockIdx.x;
    const int m3  = bid % 3;
    if (m3 == 2) {
        const int wi   = bid / 3;                 // 0..2047
        const int warp = threadIdx.x >> 5;
        const int lane = threadIdx.x & 31;
        const int base = wi * 64 + warp * 8;
#pragma unroll
        for (int it = 0; it < 8; it++) {
            const int gw = base + it;
            const int o = gw >> 5;
            const int s = gw & 31;
            const int code = __ldg(&assign[o * 32 + s]);
            const float4 v = *(const float4*)(cb + ((size_t)(s * 256 + code)) * 128 + lane * 4);
            __half2 h[2];
            h[0] = __floats2half2_rn(v.x, v.y);
            h[1] = __floats2half2_rn(v.z, v.w);
            *(uint2*)(g_Wh + (size_t)o * K_TOT + s * 128 + lane * 4) = *(const uint2*)h;
        }
    } else {
        const int xi = (bid / 3) * 2 + m3;
        const size_t n8 = (size_t)M_TOT * K_TOT / 8;
        const size_t tid0 = (size_t)xi * blockDim.x + threadIdx.x;
        const size_t stride = (size_t)4096 * blockDim.x;
        for (size_t g = tid0; g < n8; g += stride) {
            const float4 a = ((const float4*)(x + g * 8))[0];
            const float4 b = ((const float4*)(x + g * 8))[1];
            __half2 o[4];
            o[0] = __floats2half2_rn(a.x, a.y);
            o[1] = __floats2half2_rn(a.z, a.w);
            o[2] = __floats2half2_rn(b.x, b.y);
            o[3] = __floats2half2_rn(b.z, b.w);
            *(uint4*)(g_Xh + g * 8) = *(const uint4*)o;
        }
    }
}

// SW128 swizzle for the cp.async store side (off = row*128 + col_bytes)
__device__ __forceinline__ uint32_t swz(uint32_t off) {
    return off ^ ((off >> 3) & 0x70);
}

// ---------------- GEMM ----------------
__global__ __launch_bounds__(128, 2) void pq_f16_gemm(float* __restrict__ out)
{
    extern __shared__ char smem[];
    const uint32_t sbase = smem_u32(smem);

    const int tid  = threadIdx.x;
    const int wid  = tid >> 5;       // 0..3
    const int lane = tid & 31;
    const int lq   = lane >> 2;
    const int lr   = lane & 3;
    const int sel  = lane >> 3;      // ldmatrix matrix selector 0..3
    const int lrow = lane & 7;

    // grid swizzle: 8x8 tile groups
    const int bid = blockIdx.x;
    const int grp = bid >> 6;
    const int r   = bid & 63;
    const int mt  = (grp & 7) * 8 + (r & 7);
    const int nt  = (grp >> 3) * 8 + (r >> 3);
    const int m0  = mt * BM;
    const int n0  = nt * BN;

    // warp tile 64x64 (2x2 warps)
    const int wm = (wid >> 1) * 64;
    const int wn = (wid & 1) * 64;

    float acc[4][8][4];
#pragma unroll
    for (int mi = 0; mi < 4; mi++)
#pragma unroll
        for (int ni = 0; ni < 8; ni++)
#pragma unroll
            for (int q = 0; q < 4; q++) acc[mi][ni][q] = 0.f;

    // ldmatrix addr = stagebase + rowbase + ((col + ko) ^ sx),  sx=(row&7)*16
    uint32_t a_base[4], a_sx[4], b_base[4], b_sx[4];
    const uint32_t a_col = (uint32_t)((sel >> 1) << 4);
    const uint32_t b_col = (uint32_t)((sel & 1) << 4);
#pragma unroll
    for (int mi = 0; mi < 4; mi++) {
        const int row = wm + mi * 16 + ((sel & 1) << 3) + lrow;
        a_base[mi] = (uint32_t)(row * 128);
        a_sx[mi]   = (uint32_t)((row & 7) * 16);
    }
#pragma unroll
    for (int np = 0; np < 4; np++) {
        const int n = wn + np * 16 + ((sel >> 1) << 3) + lrow;
        b_base[np] = (uint32_t)(n * 128);
        b_sx[np]   = (uint32_t)((n & 7) * 16);
    }

    // cp.async mapping: per operand 1024 x 16B, 128 threads -> 8 each
    const int l_row = tid >> 3;
    const int l_c   = tid & 7;

    const __half* aptr = g_Xh + (size_t)(m0 + l_row) * K_TOT + l_c * 8;
    const __half* bptr = g_Wh + (size_t)(n0 + l_row) * K_TOT + l_c * 8;
    const uint32_t so_base[8] = {
        swz((l_row +   0) * 128 + l_c * 16), swz((l_row +  16) * 128 + l_c * 16),
        swz((l_row +  32) * 128 + l_c * 16), swz((l_row +  48) * 128 + l_c * 16),
        swz((l_row +  64) * 128 + l_c * 16), swz((l_row +  80) * 128 + l_c * 16),
        swz((l_row +  96) * 128 + l_c * 16), swz((l_row + 112) * 128 + l_c * 16)};

    auto load_stage = [&](int st, const __half* ap, const __half* bp) {
        const uint32_t ab = sbase + st * A_STAGE_BYTES;
        const uint32_t bb = sbase + SM_B_OFF + st * B_STAGE_BYTES;
#pragma unroll
        for (int p = 0; p < 8; p++) {
            cpa16(ab + so_base[p], ap + (size_t)(p * 16) * K_TOT);
            cpa16(bb + so_base[p], bp + (size_t)(p * 16) * K_TOT);
        }
    };

    const __half* ald = aptr;
    const __half* bld = bptr;
#pragma unroll
    for (int c = 0; c < STAGES - 1; c++) {
        load_stage(c, ald, bld);
        cp_commit();
        ald += BK; bld += BK;
    }

    // chunk 0 resident + visible; prefetch its k0 fragments into buffer 0
    cp_wait<1>();
    __syncthreads();

    uint32_t af[2][4][4], bf[2][4][4];
#pragma unroll
    for (int mi = 0; mi < 4; mi++)
        ldsm4(af[0][mi], sbase + a_base[mi] + (a_col ^ a_sx[mi]));
#pragma unroll
    for (int np = 0; np < 4; np++)
        ldsm4(bf[0][np], sbase + SM_B_OFF + b_base[np] + (b_col ^ b_sx[np]));

    int st = 0;                 // stage of chunk i
    int st_ld = STAGES - 1;     // stage for the next load
#pragma unroll 1
    for (int i = 0; i < NCHUNK; i++) {
        const uint32_t ab = sbase + st * A_STAGE_BYTES;
        const uint32_t bb = sbase + SM_B_OFF + st * B_STAGE_BYTES;
        const int st_n = (st == STAGES - 1) ? 0 : st + 1;
        const uint32_t ab_n = sbase + st_n * A_STAGE_BYTES;
        const uint32_t bb_n = sbase + SM_B_OFF + st_n * B_STAGE_BYTES;

        // ---- kg = 0: prefetch kg1 frags; MMA on buffer 0 ----
        {
            const uint32_t ko = 32;
#pragma unroll
            for (int mi = 0; mi < 4; mi++)
                ldsm4(af[1][mi], ab + a_base[mi] + ((a_col + ko) ^ a_sx[mi]));
#pragma unroll
            for (int np = 0; np < 4; np++)
                ldsm4(bf[1][np], bb + b_base[np] + ((b_col + ko) ^ b_sx[np]));
#pragma unroll
            for (int mi = 0; mi < 4; mi++)
#pragma unroll
                for (int ni = 0; ni < 8; ni++)
                    mma_f16(acc[mi][ni], af[0][mi], &bf[0][ni >> 1][(ni & 1) * 2]);
        }
        // ---- kg = 1: prefetch kg2 frags; MMA on buffer 1 ----
        {
            const uint32_t ko = 64;
#pragma unroll
            for (int mi = 0; mi < 4; mi++)
                ldsm4(af[0][mi], ab + a_base[mi] + ((a_col + ko) ^ a_sx[mi]));
#pragma unroll
            for (int np = 0; np < 4; np++)
                ldsm4(bf[0][np], bb + b_base[np] + ((b_col + ko) ^ b_sx[np]));
#pragma unroll
            for (int mi = 0; mi < 4; mi++)
#pragma unroll
                for (int ni = 0; ni < 8; ni++)
                    mma_f16(acc[mi][ni], af[1][mi], &bf[1][ni >> 1][(ni & 1) * 2]);
        }

        // ---- mid-chunk sync: chunk i+1 complete (pending == {c_{i+1}}) and
        //      globally visible; iter i-1's smem reads ordered before the load.
        cp_wait<0>();
        __syncthreads();
        if (i + STAGES - 1 < NCHUNK) {
            load_stage(st_ld, ald, bld);
            ald += BK; bld += BK;
        }
        cp_commit();

        // ---- kg = 2: prefetch kg3 frags; MMA on buffer 0 ----
        {
            const uint32_t ko = 96;
#pragma unroll
            for (int mi = 0; mi < 4; mi++)
                ldsm4(af[1][mi], ab + a_base[mi] + ((a_col + ko) ^ a_sx[mi]));
#pragma unroll
            for (int np = 0; np < 4; np++)
                ldsm4(bf[1][np], bb + b_base[np] + ((b_col + ko) ^ b_sx[np]));
#pragma unroll
            for (int mi = 0; mi < 4; mi++)
#pragma unroll
                for (int ni = 0; ni < 8; ni++)
                    mma_f16(acc[mi][ni], af[0][mi], &bf[0][ni >> 1][(ni & 1) * 2]);
        }
        // ---- kg = 3: prefetch chunk i+1 k0 frags (safe now); MMA on buffer 1 ----
        {
            if (i + 1 < NCHUNK) {
#pragma unroll
                for (int mi = 0; mi < 4; mi++)
                    ldsm4(af[0][mi], ab_n + a_base[mi] + (a_col ^ a_sx[mi]));
#pragma unroll
                for (int np = 0; np < 4; np++)
                    ldsm4(bf[0][np], bb_n + b_base[np] + (b_col ^ b_sx[np]));
            }
#pragma unroll
            for (int mi = 0; mi < 4; mi++)
#pragma unroll
                for (int ni = 0; ni < 8; ni++)
                    mma_f16(acc[mi][ni], af[1][mi], &bf[1][ni >> 1][(ni & 1) * 2]);
        }

        st    = st_n;
        st_ld = (st_ld == STAGES - 1) ? 0 : st_ld + 1;
    }

    // epilogue
#pragma unroll
    for (int mi = 0; mi < 4; mi++) {
#pragma unroll
        for (int ni = 0; ni < 8; ni++) {
            const int row0 = m0 + wm + mi * 16 + lq;
            const int col  = n0 + wn + ni * 8 + 2 * lr;
            *(float2*)&out[(size_t)row0 * N_TOT + col] =
                make_float2(acc[mi][ni][0], acc[mi][ni][1]);
            *(float2*)&out[(size_t)(row0 + 8) * N_TOT + col] =
                make_float2(acc[mi][ni][2], acc[mi][ni][3]);
        }
    }
}

extern "C" void kernel_launch(void* const* d_in, const int* in_sizes, int n_in,
                              void* d_out, int out_size) {
    const float* x         = (const float*)d_in[0];   // [4,2048,4096] fp32
    const float* codebooks = (const float*)d_in[1];   // [32,256,128] fp32
    const int*   assign    = (const int*)d_in[2];     // [4096,32] int32
    float*       out       = (float*)d_out;

    prep_fused_kernel<<<6144, 256>>>(x, codebooks, assign);

    cudaFuncSetAttribute(pq_f16_gemm,
                         cudaFuncAttributeMaxDynamicSharedMemorySize, SMEM_BYTES);
    pq_f16_gemm<<<(M_TOT / BM) * (N_TOT / BN), 128, SMEM_BYTES>>>(out);
}

// round 16
// speedup vs baseline: 1.0028x; 1.0028x over previous
#include <cuda_runtime.h>
#include <cuda_fp16.h>
#include <cstdint>

// PQLinear: out[8192,4096] = X[8192,4096] @ W^T (W gathered from PQ codebooks).
// R16: vs R15 (race-free, rel_err 2.937e-4):
//  - prep X-convert batched: 8 streaming float4 loads in flight per thread
//    (MLP 2 -> 8; the kernel was latency-bound at 74% DRAM)
//  - GEMM epilogue uses __stcs (output never re-read; keep L2 for A/B tiles)
//  - GEMM mainloop byte-identical to R15

#define M_TOT 8192
#define N_TOT 4096
#define K_TOT 4096
#define BM 128
#define BN 128
#define BK 64                         // halves per chunk (128 B rows)
#define STAGES 3
#define NCHUNK (K_TOT / BK)           // 64
#define A_STAGE_BYTES (BM * 128)      // 16384
#define B_STAGE_BYTES (BN * 128)      // 16384
#define SM_B_OFF (STAGES * A_STAGE_BYTES)
#define SMEM_BYTES (STAGES * (A_STAGE_BYTES + B_STAGE_BYTES))   // 98304

__device__ __half g_Xh[(size_t)M_TOT * K_TOT];   // 64 MB fp16 X
__device__ __half g_Wh[(size_t)N_TOT * K_TOT];   // 32 MB fp16 gathered W

// ---------------- helpers ----------------
__device__ __forceinline__ uint32_t smem_u32(const void* p) {
    uint32_t a;
    asm("{ .reg .u64 t; cvta.to.shared.u64 t, %1; cvt.u32.u64 %0, t; }" : "=r"(a) : "l"(p));
    return a;
}
__device__ __forceinline__ void cpa16(uint32_t saddr, const void* gaddr) {
    asm volatile("cp.async.cg.shared.global [%0], [%1], 16;" :: "r"(saddr), "l"(gaddr));
}
__device__ __forceinline__ void cp_commit() { asm volatile("cp.async.commit_group;" ::: "memory"); }
template <int N>
__device__ __forceinline__ void cp_wait() { asm volatile("cp.async.wait_group %0;" :: "n"(N) : "memory"); }

__device__ __forceinline__ void ldsm4(uint32_t* r, uint32_t addr) {
    asm volatile("ldmatrix.sync.aligned.m8n8.x4.shared.b16 {%0,%1,%2,%3}, [%4];"
                 : "=r"(r[0]), "=r"(r[1]), "=r"(r[2]), "=r"(r[3]) : "r"(addr));
}
__device__ __forceinline__ void mma_f16(float* c, const uint32_t* a, const uint32_t* b) {
    asm volatile(
        "mma.sync.aligned.m16n8k16.row.col.f32.f16.f16.f32 "
        "{%0,%1,%2,%3}, {%4,%5,%6,%7}, {%8,%9}, {%0,%1,%2,%3};"
        : "+f"(c[0]), "+f"(c[1]), "+f"(c[2]), "+f"(c[3])
        : "r"(a[0]), "r"(a[1]), "r"(a[2]), "r"(a[3]), "r"(b[0]), "r"(b[1]));
}

// ---------------- fused prep, interleaved by bid%3 ----------------
// grid = 6144 x 256: bid%3==2 -> W gather (2048 blocks), else X convert (4096)
__global__ void prep_fused_kernel(const float* __restrict__ x,
                                  const float* __restrict__ cb,
                                  const int* __restrict__ assign) {
    const int bid = blockIdx.x;
    const int m3  = bid % 3;
    if (m3 == 2) {
        const int wi   = bid / 3;                 // 0..2047
        const int warp = threadIdx.x >> 5;
        const int lane = threadIdx.x & 31;
        const int base = wi * 64 + warp * 8;
#pragma unroll
        for (int it = 0; it < 8; it++) {
            const int gw = base + it;
            const int o = gw >> 5;
            const int s = gw & 31;
            const int code = __ldg(&assign[o * 32 + s]);
            const float4 v = *(const float4*)(cb + ((size_t)(s * 256 + code)) * 128 + lane * 4);
            __half2 h[2];
            h[0] = __floats2half2_rn(v.x, v.y);
            h[1] = __floats2half2_rn(v.z, v.w);
            *(uint2*)(g_Wh + (size_t)o * K_TOT + s * 128 + lane * 4) = *(const uint2*)h;
        }
    } else {
        // X: exactly 4 groups of 8 floats per thread; batch all loads (MLP=8)
        const int xi = (bid / 3) * 2 + m3;                    // 0..4095
        const size_t tid0   = (size_t)xi * blockDim.x + threadIdx.x;
        const size_t stride = (size_t)4096 * blockDim.x;      // 1048576 threads
        float4 v[8];
#pragma unroll
        for (int j = 0; j < 4; j++) {
            const float4* s = (const float4*)(x + (tid0 + j * stride) * 8);
            v[2 * j]     = __ldcs(s);
            v[2 * j + 1] = __ldcs(s + 1);
        }
#pragma unroll
        for (int j = 0; j < 4; j++) {
            __half2 o[4];
            o[0] = __floats2half2_rn(v[2 * j].x,     v[2 * j].y);
            o[1] = __floats2half2_rn(v[2 * j].z,     v[2 * j].w);
            o[2] = __floats2half2_rn(v[2 * j + 1].x, v[2 * j + 1].y);
            o[3] = __floats2half2_rn(v[2 * j + 1].z, v[2 * j + 1].w);
            *(uint4*)(g_Xh + (tid0 + j * stride) * 8) = *(const uint4*)o;
        }
    }
}

// SW128 swizzle for the cp.async store side (off = row*128 + col_bytes)
__device__ __forceinline__ uint32_t swz(uint32_t off) {
    return off ^ ((off >> 3) & 0x70);
}

// ---------------- GEMM ----------------
__global__ __launch_bounds__(128, 2) void pq_f16_gemm(float* __restrict__ out)
{
    extern __shared__ char smem[];
    const uint32_t sbase = smem_u32(smem);

    const int tid  = threadIdx.x;
    const int wid  = tid >> 5;       // 0..3
    const int lane = tid & 31;
    const int lq   = lane >> 2;
    const int lr   = lane & 3;
    const int sel  = lane >> 3;      // ldmatrix matrix selector 0..3
    const int lrow = lane & 7;

    // grid swizzle: 8x8 tile groups
    const int bid = blockIdx.x;
    const int grp = bid >> 6;
    const int r   = bid & 63;
    const int mt  = (grp & 7) * 8 + (r & 7);
    const int nt  = (grp >> 3) * 8 + (r >> 3);
    const int m0  = mt * BM;
    const int n0  = nt * BN;

    // warp tile 64x64 (2x2 warps)
    const int wm = (wid >> 1) * 64;
    const int wn = (wid & 1) * 64;

    float acc[4][8][4];
#pragma unroll
    for (int mi = 0; mi < 4; mi++)
#pragma unroll
        for (int ni = 0; ni < 8; ni++)
#pragma unroll
            for (int q = 0; q < 4; q++) acc[mi][ni][q] = 0.f;

    // ldmatrix addr = stagebase + rowbase + ((col + ko) ^ sx),  sx=(row&7)*16
    uint32_t a_base[4], a_sx[4], b_base[4], b_sx[4];
    const uint32_t a_col = (uint32_t)((sel >> 1) << 4);
    const uint32_t b_col = (uint32_t)((sel & 1) << 4);
#pragma unroll
    for (int mi = 0; mi < 4; mi++) {
        const int row = wm + mi * 16 + ((sel & 1) << 3) + lrow;
        a_base[mi] = (uint32_t)(row * 128);
        a_sx[mi]   = (uint32_t)((row & 7) * 16);
    }
#pragma unroll
    for (int np = 0; np < 4; np++) {
        const int n = wn + np * 16 + ((sel >> 1) << 3) + lrow;
        b_base[np] = (uint32_t)(n * 128);
        b_sx[np]   = (uint32_t)((n & 7) * 16);
    }

    // cp.async mapping: per operand 1024 x 16B, 128 threads -> 8 each
    const int l_row = tid >> 3;
    const int l_c   = tid & 7;

    const __half* aptr = g_Xh + (size_t)(m0 + l_row) * K_TOT + l_c * 8;
    const __half* bptr = g_Wh + (size_t)(n0 + l_row) * K_TOT + l_c * 8;
    const uint32_t so_base[8] = {
        swz((l_row +   0) * 128 + l_c * 16), swz((l_row +  16) * 128 + l_c * 16),
        swz((l_row +  32) * 128 + l_c * 16), swz((l_row +  48) * 128 + l_c * 16),
        swz((l_row +  64) * 128 + l_c * 16), swz((l_row +  80) * 128 + l_c * 16),
        swz((l_row +  96) * 128 + l_c * 16), swz((l_row + 112) * 128 + l_c * 16)};

    auto load_stage = [&](int st, const __half* ap, const __half* bp) {
        const uint32_t ab = sbase + st * A_STAGE_BYTES;
        const uint32_t bb = sbase + SM_B_OFF + st * B_STAGE_BYTES;
#pragma unroll
        for (int p = 0; p < 8; p++) {
            cpa16(ab + so_base[p], ap + (size_t)(p * 16) * K_TOT);
            cpa16(bb + so_base[p], bp + (size_t)(p * 16) * K_TOT);
        }
    };

    const __half* ald = aptr;
    const __half* bld = bptr;
#pragma unroll
    for (int c = 0; c < STAGES - 1; c++) {
        load_stage(c, ald, bld);
        cp_commit();
        ald += BK; bld += BK;
    }

    // chunk 0 resident + visible; prefetch its k0 fragments into buffer 0
    cp_wait<1>();
    __syncthreads();

    uint32_t af[2][4][4], bf[2][4][4];
#pragma unroll
    for (int mi = 0; mi < 4; mi++)
        ldsm4(af[0][mi], sbase + a_base[mi] + (a_col ^ a_sx[mi]));
#pragma unroll
    for (int np = 0; np < 4; np++)
        ldsm4(bf[0][np], sbase + SM_B_OFF + b_base[np] + (b_col ^ b_sx[np]));

    int st = 0;                 // stage of chunk i
    int st_ld = STAGES - 1;     // stage for the next load
#pragma unroll 1
    for (int i = 0; i < NCHUNK; i++) {
        const uint32_t ab = sbase + st * A_STAGE_BYTES;
        const uint32_t bb = sbase + SM_B_OFF + st * B_STAGE_BYTES;
        const int st_n = (st == STAGES - 1) ? 0 : st + 1;
        const uint32_t ab_n = sbase + st_n * A_STAGE_BYTES;
        const uint32_t bb_n = sbase + SM_B_OFF + st_n * B_STAGE_BYTES;

        // ---- kg = 0: prefetch kg1 frags; MMA on buffer 0 ----
        {
            const uint32_t ko = 32;
#pragma unroll
            for (int mi = 0; mi < 4; mi++)
                ldsm4(af[1][mi], ab + a_base[mi] + ((a_col + ko) ^ a_sx[mi]));
#pragma unroll
            for (int np = 0; np < 4; np++)
                ldsm4(bf[1][np], bb + b_base[np] + ((b_col + ko) ^ b_sx[np]));
#pragma unroll
            for (int mi = 0; mi < 4; mi++)
#pragma unroll
                for (int ni = 0; ni < 8; ni++)
                    mma_f16(acc[mi][ni], af[0][mi], &bf[0][ni >> 1][(ni & 1) * 2]);
        }
        // ---- kg = 1: prefetch kg2 frags; MMA on buffer 1 ----
        {
            const uint32_t ko = 64;
#pragma unroll
            for (int mi = 0; mi < 4; mi++)
                ldsm4(af[0][mi], ab + a_base[mi] + ((a_col + ko) ^ a_sx[mi]));
#pragma unroll
            for (int np = 0; np < 4; np++)
                ldsm4(bf[0][np], bb + b_base[np] + ((b_col + ko) ^ b_sx[np]));
#pragma unroll
            for (int mi = 0; mi < 4; mi++)
#pragma unroll
                for (int ni = 0; ni < 8; ni++)
                    mma_f16(acc[mi][ni], af[1][mi], &bf[1][ni >> 1][(ni & 1) * 2]);
        }

        // ---- mid-chunk sync: chunk i+1 complete and globally visible; iter
        //      i-1's smem reads ordered before the stage st_ld overwrite.
        cp_wait<0>();
        __syncthreads();
        if (i + STAGES - 1 < NCHUNK) {
            load_stage(st_ld, ald, bld);
            ald += BK; bld += BK;
        }
        cp_commit();

        // ---- kg = 2: prefetch kg3 frags; MMA on buffer 0 ----
        {
            const uint32_t ko = 96;
#pragma unroll
            for (int mi = 0; mi < 4; mi++)
                ldsm4(af[1][mi], ab + a_base[mi] + ((a_col + ko) ^ a_sx[mi]));
#pragma unroll
            for (int np = 0; np < 4; np++)
                ldsm4(bf[1][np], bb + b_base[np] + ((b_col + ko) ^ b_sx[np]));
#pragma unroll
            for (int mi = 0; mi < 4; mi++)
#pragma unroll
                for (int ni = 0; ni < 8; ni++)
                    mma_f16(acc[mi][ni], af[0][mi], &bf[0][ni >> 1][(ni & 1) * 2]);
        }
        // ---- kg = 3: prefetch chunk i+1 k0 frags (visible since the barrier);
        //      MMA on buffer 1 ----
        {
            if (i + 1 < NCHUNK) {
#pragma unroll
                for (int mi = 0; mi < 4; mi++)
                    ldsm4(af[0][mi], ab_n + a_base[mi] + (a_col ^ a_sx[mi]));
#pragma unroll
                for (int np = 0; np < 4; np++)
                    ldsm4(bf[0][np], bb_n + b_base[np] + (b_col ^ b_sx[np]));
            }
#pragma unroll
            for (int mi = 0; mi < 4; mi++)
#pragma unroll
                for (int ni = 0; ni < 8; ni++)
                    mma_f16(acc[mi][ni], af[1][mi], &bf[1][ni >> 1][(ni & 1) * 2]);
        }

        st    = st_n;
        st_ld = (st_ld == STAGES - 1) ? 0 : st_ld + 1;
    }

    // epilogue: streaming stores (output never re-read)
#pragma unroll
    for (int mi = 0; mi < 4; mi++) {
#pragma unroll
        for (int ni = 0; ni < 8; ni++) {
            const int row0 = m0 + wm + mi * 16 + lq;
            const int col  = n0 + wn + ni * 8 + 2 * lr;
            __stcs((float2*)&out[(size_t)row0 * N_TOT + col],
                   make_float2(acc[mi][ni][0], acc[mi][ni][1]));
            __stcs((float2*)&out[(size_t)(row0 + 8) * N_TOT + col],
                   make_float2(acc[mi][ni][2], acc[mi][ni][3]));
        }
    }
}

extern "C" void kernel_launch(void* const* d_in, const int* in_sizes, int n_in,
                              void* d_out, int out_size) {
    const float* x         = (const float*)d_in[0];   // [4,2048,4096] fp32
    const float* codebooks = (const float*)d_in[1];   // [32,256,128] fp32
    const int*   assign    = (const int*)d_in[2];     // [4096,32] int32
    float*       out       = (float*)d_out;

    prep_fused_kernel<<<6144, 256>>>(x, codebooks, assign);

    cudaFuncSetAttribute(pq_f16_gemm,
                         cudaFuncAttributeMaxDynamicSharedMemorySize, SMEM_BYTES);
    pq_f16_gemm<<<(M_TOT / BM) * (N_TOT / BN), 128, SMEM_BYTES>>>(out);
}